// round 7
// baseline (speedup 1.0000x reference)
#include <cuda_runtime.h>

#define BN   8
#define NP   2048
#define DETK 100
#define NTH  256
#define EPT  8
#define FULL 0xffffffffu

static __device__ __forceinline__ float stable_sigmoid(float d) {
    return (d >= 0.0f) ? (1.0f / (1.0f + expf(-d)))
                       : (expf(d) / (1.0f + expf(d)));
}
static __device__ __forceinline__ unsigned f2s(float f) {
    unsigned u = __float_as_uint(f);
    return (u & 0x80000000u) ? ~u : (u | 0x80000000u);
}
static __device__ __forceinline__ float s2f(unsigned u) {
    u = (u & 0x80000000u) ? (u & 0x7FFFFFFFu) : ~u;
    return __uint_as_float(u);
}

struct Smem {
    float4             sbox[NP];       // decoded+clipped boxes, original order (32 KB)
    float4             kbox[DETK];     // kept boxes, keep order
    float4             swbox[32];      // window scratch boxes
    unsigned long long kbuf[2][NP];    // sort exchange buffers (32 KB)
    float              karea[DETK];
    unsigned           keepkey[DETK];
    float              swarea[32];
    int                cnt;
};

__global__ __launch_bounds__(NTH, 1)
void seas_postprocess_kernel(const float* __restrict__ clss,
                             const float* __restrict__ regs,
                             const float* __restrict__ qlts,
                             const float* __restrict__ props,
                             float* __restrict__ out)
{
    extern __shared__ unsigned char smem_raw[];
    Smem& sm = *reinterpret_cast<Smem*>(smem_raw);

    const int b    = blockIdx.x;
    const int tid  = threadIdx.x;
    const int lane = tid & 31;

    const float W_IMG = 1344.0f, H_IMG = 800.0f;
    const float CLIPV = 4.135166556742356f;  // log(1000/16)

    const float2* cls = (const float2*)(clss  + (size_t)b * NP * 2);
    const float4* reg = (const float4*)(regs  + (size_t)b * NP * 4);
    const float*  qlt =                 qlts  + (size_t)b * NP;
    const float4* prp = (const float4*)(props + (size_t)b * NP * 4);

    // ---- Phase 1: decode, clip, score (math bit-identical to prior rounds) ----
    unsigned long long ekey[EPT];
    #pragma unroll
    for (int e = 0; e < EPT; ++e) {
        int j = (e << 8) | tid;
        float4 p = prp[j];
        float bw = p.z - p.x, bh = p.w - p.y;
        float cx = p.x + 0.5f * bw, cy = p.y + 0.5f * bh;

        float4 r = reg[j];
        float dx = r.x * 0.1f;
        float dy = r.y * 0.1f;
        float dw = fminf(r.z * 0.2f, CLIPV);
        float dh = fminf(r.w * 0.2f, CLIPV);

        float pcx = dx * bw + cx;
        float pcy = dy * bh + cy;
        float pw  = expf(dw) * bw;
        float ph  = expf(dh) * bh;

        float x1 = fminf(fmaxf(pcx - 0.5f * pw, 0.0f), W_IMG);
        float y1 = fminf(fmaxf(pcy - 0.5f * ph, 0.0f), H_IMG);
        float x2 = fminf(fmaxf(pcx + 0.5f * pw, 0.0f), W_IMG);
        float y2 = fminf(fmaxf(pcy + 0.5f * ph, 0.0f), H_IMG);

        bool small_keep = ((x2 - x1) >= 0.01f) && ((y2 - y1) >= 0.01f);

        float2 c = cls[j];
        float raw = stable_sigmoid(c.y - c.x);
        bool  score_keep = raw > 0.5f;
        float score = stable_sigmoid(qlt[j]) * raw;

        bool valid = small_keep && score_keep;
        unsigned k32 = valid ? f2s(score) : 0u;   // valid <=> k32 >= 0x80000000

        sm.sbox[j] = make_float4(x1, y1, x2, y2);
        ekey[e] = ((unsigned long long)k32 << 32) | (unsigned)(NP - 1 - j);
    }
    if (tid == 0) sm.cnt = 0;

    // ---- Phase 2: hybrid bitonic sort, descending (same network, new mapping) ----
    // element idx = (e<<8)|tid. takemax = ((idx&k)==0) != ((idx&jj)!=0)
    int cur = 0;
    #pragma unroll
    for (int k = 2; k <= NP; k <<= 1) {
        #pragma unroll
        for (int jj = k >> 1; jj > 0; jj >>= 1) {
            if (jj >= NTH) {
                // in-thread: partner element e ^ (jj>>8); lower has jj-bit 0 -> up=false
                int d = jj >> 8;
                #pragma unroll
                for (int e = 0; e < EPT; ++e) {
                    if ((e & d) == 0) {
                        bool tm = (((e << 8) & k) == 0);   // tid bits < 256 <= k here
                        unsigned long long a  = ekey[e];
                        unsigned long long c2 = ekey[e | d];
                        unsigned long long mx = a > c2 ? a : c2;
                        unsigned long long mn = a > c2 ? c2 : a;
                        ekey[e]     = tm ? mx : mn;
                        ekey[e | d] = tm ? mn : mx;
                    }
                }
            } else if (jj >= 32) {
                // smem exchange, one 8-warp barrier
                #pragma unroll
                for (int e = 0; e < EPT; ++e) sm.kbuf[cur][(e << 8) | tid] = ekey[e];
                __syncthreads();
                #pragma unroll
                for (int e = 0; e < EPT; ++e) {
                    int idx = (e << 8) | tid;
                    unsigned long long p = sm.kbuf[cur][idx ^ jj];
                    bool tm = ((idx & k) == 0) != ((tid & jj) != 0);
                    ekey[e] = tm ? (ekey[e] > p ? ekey[e] : p)
                                 : (ekey[e] < p ? ekey[e] : p);
                }
                cur ^= 1;
            } else {
                // intra-warp shfl exchange
                #pragma unroll
                for (int e = 0; e < EPT; ++e) {
                    unsigned long long p = __shfl_xor_sync(FULL, ekey[e], jj);
                    bool tm = (((((e << 8) | tid)) & k) == 0) != ((lane & jj) != 0);
                    ekey[e] = tm ? (ekey[e] > p ? ekey[e] : p)
                                 : (ekey[e] < p ? ekey[e] : p);
                }
            }
        }
    }
    // publish sorted keys
    #pragma unroll
    for (int e = 0; e < EPT; ++e) sm.kbuf[cur][(e << 8) | tid] = ekey[e];
    __syncthreads();
    const unsigned long long* kk = sm.kbuf[cur];

    // ---- Phase 3: single-warp windowed greedy NMS ----
    if (tid < 32) {
        int cnt = 0;
        for (int p = 0; p < NP && cnt < DETK; p += 32) {
            unsigned long long key = kk[p + lane];
            unsigned k32 = (unsigned)(key >> 32);
            bool valid = k32 >= 0x80000000u;
            if (__ballot_sync(FULL, valid) == 0) break;  // sorted: rest invalid

            int orig = NP - 1 - (int)(unsigned)key;
            float4 bx = sm.sbox[orig];
            float  ar = (bx.z - bx.x) * (bx.w - bx.y);
            float  ap = ar + 1e-9f;

            // vs previously kept boxes
            bool sup = false;
            #pragma unroll 4
            for (int t = 0; t < cnt; ++t) {
                float4 kb = sm.kbox[t];
                float  ka = sm.karea[t];
                float iw = fmaxf(fminf(kb.z, bx.z) - fmaxf(kb.x, bx.x), 0.0f);
                float ih = fmaxf(fminf(kb.w, bx.w) - fmaxf(kb.y, bx.y), 0.0f);
                sup = sup || (3.5f * (iw * ih) > ka + ap);   // iou > 0.4
            }

            // intra-window suppression mask (bits i < lane only)
            sm.swbox[lane]  = bx;
            sm.swarea[lane] = ar;
            __syncwarp();
            unsigned supmask = 0u;
            #pragma unroll 8
            for (int i = 0; i < 32; ++i) {
                float4 b2 = sm.swbox[i];
                float  a2 = sm.swarea[i];
                float iw = fmaxf(fminf(b2.z, bx.z) - fmaxf(b2.x, bx.x), 0.0f);
                float ih = fmaxf(fminf(b2.w, bx.w) - fmaxf(b2.y, bx.y), 0.0f);
                bool s = (3.5f * (iw * ih) > a2 + ap) && (i < lane);
                supmask |= s ? (1u << i) : 0u;
            }

            // greedy resolve via ballots
            unsigned alive = __ballot_sync(FULL, valid && !sup);
            while (alive && cnt < DETK) {
                int i = __ffs(alive) - 1;
                if (lane == i) {
                    sm.kbox[cnt]    = bx;
                    sm.karea[cnt]   = ar;
                    sm.keepkey[cnt] = k32;
                }
                unsigned dead = __ballot_sync(FULL, (supmask >> i) & 1u);
                alive &= ~dead & ~(1u << i);
                cnt++;
            }
            __syncwarp();
        }
        if (lane == 0) sm.cnt = cnt;
    }
    __syncthreads();

    // ---- Phase 4: outputs [boxes 3200 | scores 800 | classes 800 | valid 800] ----
    if (tid < DETK) {
        int k = tid;
        float4 ob = make_float4(0.f, 0.f, 0.f, 0.f);
        float os = 0.f, oc = 0.f, ov = 0.f;
        if (k < sm.cnt) {
            ob = sm.kbox[k];
            os = s2f(sm.keepkey[k]);
            oc = 1.0f;
            ov = 1.0f;
        }
        float* obp = out + ((size_t)b * DETK + k) * 4;
        obp[0] = ob.x; obp[1] = ob.y; obp[2] = ob.z; obp[3] = ob.w;
        const int SB = BN * DETK * 4;   // 3200
        const int SC = BN * DETK;       // 800
        out[SB +          b * DETK + k] = os;
        out[SB + SC +     b * DETK + k] = oc;
        out[SB + 2 * SC + b * DETK + k] = ov;
    }
}

extern "C" void kernel_launch(void* const* d_in, const int* in_sizes, int n_in,
                              void* d_out, int out_size) {
    const float* clss  = (const float*)d_in[0];
    const float* regs  = (const float*)d_in[1];
    const float* qlts  = (const float*)d_in[2];
    const float* props = (const float*)d_in[3];
    float* out = (float*)d_out;

    size_t smem = sizeof(Smem);
    cudaFuncSetAttribute(seas_postprocess_kernel,
                         cudaFuncAttributeMaxDynamicSharedMemorySize, (int)smem);
    seas_postprocess_kernel<<<BN, NTH, smem>>>(clss, regs, qlts, props, out);
}

// round 8
// speedup vs baseline: 1.1720x; 1.1720x over previous
#include <cuda_runtime.h>

#define BN   8
#define NP   2048
#define DETK 100
#define NT   1024
#define FULL 0xffffffffu

static __device__ __forceinline__ float stable_sigmoid(float d) {
    return (d >= 0.0f) ? (1.0f / (1.0f + expf(-d)))
                       : (expf(d) / (1.0f + expf(d)));
}
static __device__ __forceinline__ unsigned f2s(float f) {
    unsigned u = __float_as_uint(f);
    return (u & 0x80000000u) ? ~u : (u | 0x80000000u);
}
static __device__ __forceinline__ float s2f(unsigned u) {
    u = (u & 0x80000000u) ? (u & 0x7FFFFFFFu) : ~u;
    return __uint_as_float(u);
}

struct Smem {
    float4             sbox[NP];       // decoded+clipped boxes, original order (32 KB)
    unsigned long long kbuf[2][NP];    // sort exchange buffers (32 KB)
    float4             kbox[DETK];     // kept boxes, keep order
    float              karea[DETK];
    unsigned           keepkey[DETK];
    // per-window scratch
    float4             swbox[32];
    float              swarea[32];
    unsigned           swkey[32];
    unsigned           swsup[32];      // intra-window suppression masks
    int                swok[32];       // valid && !sup-by-keeps
    int                cnt;
    int                stop;
};

__global__ __launch_bounds__(NT, 1)
void seas_postprocess_kernel(const float* __restrict__ clss,
                             const float* __restrict__ regs,
                             const float* __restrict__ qlts,
                             const float* __restrict__ props,
                             float* __restrict__ out)
{
    extern __shared__ unsigned char smem_raw[];
    Smem& sm = *reinterpret_cast<Smem*>(smem_raw);

    const int b    = blockIdx.x;
    const int tid  = threadIdx.x;
    const int w    = tid >> 5;
    const int lane = tid & 31;

    const float W_IMG = 1344.0f, H_IMG = 800.0f;
    const float CLIPV = 4.135166556742356f;  // log(1000/16)

    const float2* cls = (const float2*)(clss  + (size_t)b * NP * 2);
    const float4* reg = (const float4*)(regs  + (size_t)b * NP * 4);
    const float*  qlt =                 qlts  + (size_t)b * NP;
    const float4* prp = (const float4*)(props + (size_t)b * NP * 4);

    // ---- Phase 1: decode, clip, score (bit-identical math) ----
    unsigned long long ekey[2];
    #pragma unroll
    for (int e = 0; e < 2; ++e) {
        int j = e * NT + tid;
        float4 p = prp[j];
        float bw = p.z - p.x, bh = p.w - p.y;
        float cx = p.x + 0.5f * bw, cy = p.y + 0.5f * bh;

        float4 r = reg[j];
        float dx = r.x * 0.1f;
        float dy = r.y * 0.1f;
        float dw = fminf(r.z * 0.2f, CLIPV);
        float dh = fminf(r.w * 0.2f, CLIPV);

        float pcx = dx * bw + cx;
        float pcy = dy * bh + cy;
        float pw  = expf(dw) * bw;
        float ph  = expf(dh) * bh;

        float x1 = fminf(fmaxf(pcx - 0.5f * pw, 0.0f), W_IMG);
        float y1 = fminf(fmaxf(pcy - 0.5f * ph, 0.0f), H_IMG);
        float x2 = fminf(fmaxf(pcx + 0.5f * pw, 0.0f), W_IMG);
        float y2 = fminf(fmaxf(pcy + 0.5f * ph, 0.0f), H_IMG);

        bool small_keep = ((x2 - x1) >= 0.01f) && ((y2 - y1) >= 0.01f);

        float2 c = cls[j];
        float raw = stable_sigmoid(c.y - c.x);
        bool  score_keep = raw > 0.5f;
        float score = stable_sigmoid(qlt[j]) * raw;

        bool valid = small_keep && score_keep;
        unsigned k32 = valid ? f2s(score) : 0u;   // valid <=> k32 >= 0x80000000

        sm.sbox[j] = make_float4(x1, y1, x2, y2);
        ekey[e] = ((unsigned long long)k32 << 32) | (unsigned)(NP - 1 - j);
    }
    if (tid == 0) { sm.cnt = 0; sm.stop = 0; }

    // ---- Phase 2: hybrid bitonic sort, descending (R6 shape) ----
    int cur = 0;
    #pragma unroll
    for (int k = 2; k <= NP; k <<= 1) {
        #pragma unroll
        for (int jj = k >> 1; jj > 0; jj >>= 1) {
            if (jj == 1024) {
                unsigned long long mx = ekey[0] > ekey[1] ? ekey[0] : ekey[1];
                unsigned long long mn = ekey[0] > ekey[1] ? ekey[1] : ekey[0];
                ekey[0] = mx; ekey[1] = mn;
            } else if (jj >= 32) {
                sm.kbuf[cur][tid]      = ekey[0];
                sm.kbuf[cur][tid + NT] = ekey[1];
                __syncthreads();
                unsigned long long p0 = sm.kbuf[cur][tid ^ jj];
                unsigned long long p1 = sm.kbuf[cur][(tid + NT) ^ jj];
                bool up = (tid & jj) != 0;
                bool tm0 = ((tid & k) == 0) != up;
                bool tm1 = (((tid + NT) & k) == 0) != up;
                ekey[0] = tm0 ? (ekey[0] > p0 ? ekey[0] : p0) : (ekey[0] < p0 ? ekey[0] : p0);
                ekey[1] = tm1 ? (ekey[1] > p1 ? ekey[1] : p1) : (ekey[1] < p1 ? ekey[1] : p1);
                cur ^= 1;
            } else {
                unsigned long long p0 = __shfl_xor_sync(FULL, ekey[0], jj);
                unsigned long long p1 = __shfl_xor_sync(FULL, ekey[1], jj);
                bool up = (lane & jj) != 0;
                bool tm0 = ((tid & k) == 0) != up;
                bool tm1 = (((tid + NT) & k) == 0) != up;
                ekey[0] = tm0 ? (ekey[0] > p0 ? ekey[0] : p0) : (ekey[0] < p0 ? ekey[0] : p0);
                ekey[1] = tm1 ? (ekey[1] > p1 ? ekey[1] : p1) : (ekey[1] < p1 ? ekey[1] : p1);
            }
        }
    }
    sm.kbuf[cur][tid]      = ekey[0];
    sm.kbuf[cur][tid + NT] = ekey[1];
    __syncthreads();
    const unsigned long long* kk = sm.kbuf[cur];

    // ---- Phase 3: block-parallel windowed greedy NMS (warp w = candidate p+w) ----
    int cnt = 0;
    for (int p = 0; p < NP; p += 32) {
        unsigned long long key = kk[p + w];            // uniform per warp
        unsigned k32 = (unsigned)(key >> 32);
        bool valid = k32 >= 0x80000000u;
        int orig = NP - 1 - (int)(unsigned)key;
        float4 bx = sm.sbox[orig];
        float  ar = (bx.z - bx.x) * (bx.w - bx.y);
        float  ap = ar + 1e-9f;

        if (lane == 0) { sm.swbox[w] = bx; sm.swarea[w] = ar; sm.swkey[w] = k32; }

        // vs previously kept boxes: lanes split the keeps
        bool sup = false;
        if (valid) {
            #pragma unroll 4
            for (int t = lane; t < cnt; t += 32) {
                float4 kb = sm.kbox[t];
                float  ka = sm.karea[t];
                float iw = fmaxf(fminf(kb.z, bx.z) - fmaxf(kb.x, bx.x), 0.0f);
                float ih = fmaxf(fminf(kb.w, bx.w) - fmaxf(kb.y, bx.y), 0.0f);
                sup = sup || (3.5f * (iw * ih) > ka + ap);   // iou > 0.4
            }
        }
        sup = __any_sync(FULL, sup);
        __syncthreads();                                // swbox/swarea visible

        // intra-window: lane i tests peer i suppressing candidate w (i < w)
        unsigned supmask = 0u;
        {
            float4 b2 = sm.swbox[lane];
            float  a2 = sm.swarea[lane];
            float iw = fmaxf(fminf(b2.z, bx.z) - fmaxf(b2.x, bx.x), 0.0f);
            float ih = fmaxf(fminf(b2.w, bx.w) - fmaxf(b2.y, bx.y), 0.0f);
            bool s = (3.5f * (iw * ih) > a2 + ap) && (lane < w);
            supmask = __ballot_sync(FULL, s);
        }
        if (lane == 0) {
            sm.swsup[w] = supmask;
            sm.swok[w]  = (valid && !sup) ? 1 : 0;
        }
        __syncthreads();                                // results visible

        // warp 0 resolves greedy order within the window
        if (w == 0) {
            bool rawv  = sm.swkey[lane] >= 0x80000000u; // window validity (prefix prop.)
            unsigned vmask = __ballot_sync(FULL, rawv);
            unsigned mysup = sm.swsup[lane];
            unsigned alive = __ballot_sync(FULL, sm.swok[lane] != 0);
            int c2 = cnt;
            while (alive && c2 < DETK) {
                int i = __ffs(alive) - 1;
                if (lane == i) {
                    sm.kbox[c2]    = sm.swbox[i];
                    sm.karea[c2]   = sm.swarea[i];
                    sm.keepkey[c2] = sm.swkey[i];
                }
                unsigned dead = __ballot_sync(FULL, (mysup >> i) & 1u);
                alive &= ~dead & ~(1u << i);
                c2++;
            }
            if (lane == 0) {
                sm.cnt  = c2;
                sm.stop = (c2 >= DETK || vmask != FULL) ? 1 : 0;
            }
        }
        __syncthreads();                                // cnt/kbox/stop visible
        cnt = sm.cnt;
        if (sm.stop) break;
    }

    // ---- Phase 4: outputs [boxes 3200 | scores 800 | classes 800 | valid 800] ----
    if (tid < DETK) {
        int k = tid;
        float4 ob = make_float4(0.f, 0.f, 0.f, 0.f);
        float os = 0.f, oc = 0.f, ov = 0.f;
        if (k < cnt) {
            ob = sm.kbox[k];
            os = s2f(sm.keepkey[k]);
            oc = 1.0f;
            ov = 1.0f;
        }
        float* obp = out + ((size_t)b * DETK + k) * 4;
        obp[0] = ob.x; obp[1] = ob.y; obp[2] = ob.z; obp[3] = ob.w;
        const int SB = BN * DETK * 4;   // 3200
        const int SC = BN * DETK;       // 800
        out[SB +          b * DETK + k] = os;
        out[SB + SC +     b * DETK + k] = oc;
        out[SB + 2 * SC + b * DETK + k] = ov;
    }
}

extern "C" void kernel_launch(void* const* d_in, const int* in_sizes, int n_in,
                              void* d_out, int out_size) {
    const float* clss  = (const float*)d_in[0];
    const float* regs  = (const float*)d_in[1];
    const float* qlts  = (const float*)d_in[2];
    const float* props = (const float*)d_in[3];
    float* out = (float*)d_out;

    size_t smem = sizeof(Smem);
    cudaFuncSetAttribute(seas_postprocess_kernel,
                         cudaFuncAttributeMaxDynamicSharedMemorySize, (int)smem);
    seas_postprocess_kernel<<<BN, NT, smem>>>(clss, regs, qlts, props, out);
}

// round 9
// speedup vs baseline: 1.2655x; 1.0798x over previous
#include <cuda_runtime.h>

#define BN   8
#define NP   2048
#define DETK 100
#define NT   1024
#define FULL 0xffffffffu

typedef unsigned long long ull;

// Inter-kernel scratch (allocation-free: __device__ globals)
__device__ ull    g_keys[BN * NP];
__device__ float4 g_box [BN * NP];

static __device__ __forceinline__ float stable_sigmoid(float d) {
    return (d >= 0.0f) ? (1.0f / (1.0f + expf(-d)))
                       : (expf(d) / (1.0f + expf(d)));
}
static __device__ __forceinline__ unsigned f2s(float f) {
    unsigned u = __float_as_uint(f);
    return (u & 0x80000000u) ? ~u : (u | 0x80000000u);
}
static __device__ __forceinline__ float s2f(unsigned u) {
    u = (u & 0x80000000u) ? (u & 0x7FFFFFFFu) : ~u;
    return __uint_as_float(u);
}

// ---------------- Kernel 1: decode half-image + sort its 1024 keys ----------------
__global__ __launch_bounds__(NT, 1)
void k1_decode_sort(const float* __restrict__ clss,
                    const float* __restrict__ regs,
                    const float* __restrict__ qlts,
                    const float* __restrict__ props)
{
    __shared__ ull kb[2][NT];

    const int b    = blockIdx.x >> 1;
    const int h    = blockIdx.x & 1;
    const int tid  = threadIdx.x;
    const int lane = tid & 31;
    const int g    = (h << 10) | tid;      // global proposal index within image

    const float W_IMG = 1344.0f, H_IMG = 800.0f;
    const float CLIPV = 4.135166556742356f;   // log(1000/16)

    const float2* cls = (const float2*)(clss  + (size_t)b * NP * 2);
    const float4* reg = (const float4*)(regs  + (size_t)b * NP * 4);
    const float*  qlt =                 qlts  + (size_t)b * NP;
    const float4* prp = (const float4*)(props + (size_t)b * NP * 4);

    // ---- decode, clip, score (bit-identical math to prior rounds) ----
    float4 p = prp[g];
    float bw = p.z - p.x, bh = p.w - p.y;
    float cx = p.x + 0.5f * bw, cy = p.y + 0.5f * bh;

    float4 r = reg[g];
    float dx = r.x * 0.1f;
    float dy = r.y * 0.1f;
    float dw = fminf(r.z * 0.2f, CLIPV);
    float dh = fminf(r.w * 0.2f, CLIPV);

    float pcx = dx * bw + cx;
    float pcy = dy * bh + cy;
    float pw  = expf(dw) * bw;
    float ph  = expf(dh) * bh;

    float x1 = fminf(fmaxf(pcx - 0.5f * pw, 0.0f), W_IMG);
    float y1 = fminf(fmaxf(pcy - 0.5f * ph, 0.0f), H_IMG);
    float x2 = fminf(fmaxf(pcx + 0.5f * pw, 0.0f), W_IMG);
    float y2 = fminf(fmaxf(pcy + 0.5f * ph, 0.0f), H_IMG);

    bool small_keep = ((x2 - x1) >= 0.01f) && ((y2 - y1) >= 0.01f);

    float2 c = cls[g];
    float raw = stable_sigmoid(c.y - c.x);
    bool  score_keep = raw > 0.5f;
    float score = stable_sigmoid(qlt[g]) * raw;

    bool valid = small_keep && score_keep;
    unsigned k32 = valid ? f2s(score) : 0u;   // valid <=> k32 >= 0x80000000

    g_box[b * NP + g] = make_float4(x1, y1, x2, y2);
    ull key = ((ull)k32 << 32) | (unsigned)(NP - 1 - g);

    // ---- bitonic sort of this half's 1024 keys (1 key/thread) ----
    // Direction from GLOBAL index g: identical to the standard 2048 network's
    // state after phases k<=1024 (half 0 descending, half 1 ascending).
    int cur = 0;
    #pragma unroll
    for (int k = 2; k <= 1024; k <<= 1) {
        #pragma unroll
        for (int jj = k >> 1; jj > 0; jj >>= 1) {
            if (jj >= 32) {
                kb[cur][tid] = key;
                __syncthreads();
                ull pk = kb[cur][tid ^ jj];
                bool tm = ((g & k) == 0) != ((tid & jj) != 0);
                key = tm ? (key > pk ? key : pk) : (key < pk ? key : pk);
                cur ^= 1;
            } else {
                ull pk = __shfl_xor_sync(FULL, key, jj);
                bool tm = ((g & k) == 0) != ((lane & jj) != 0);
                key = tm ? (key > pk ? key : pk) : (key < pk ? key : pk);
            }
        }
    }
    g_keys[b * NP + g] = key;
}

// ---------------- Kernel 2: merge phase + NMS + output ----------------
struct Smem2 {
    ull      kbuf[2][NP];      // merge exchange buffers (32 KB)
    float4   kbox[DETK];
    float4   swbox[32];
    float    karea[DETK];
    unsigned keepkey[DETK];
    float    swarea[32];
    int      cnt;
};

__global__ __launch_bounds__(NT, 1)
void k2_merge_nms(float* __restrict__ out)
{
    __shared__ Smem2 sm;

    const int b    = blockIdx.x;
    const int tid  = threadIdx.x;
    const int w    = tid >> 5;
    const int lane = tid & 31;

    ull e0 = g_keys[b * NP + tid];
    ull e1 = g_keys[b * NP + NT + tid];
    if (tid == 0) sm.cnt = 0;

    // ---- final bitonic merge phase k=2048 (thread owns slots tid, tid+1024) ----
    // tm = ((idx & 2048)==0) != ((idx & jj)!=0) = !((idx & jj)!=0)
    {   // jj = 1024: in-thread
        ull mx = e0 > e1 ? e0 : e1;
        ull mn = e0 > e1 ? e1 : e0;
        e0 = mx; e1 = mn;
    }
    int cur = 0;
    #pragma unroll
    for (int jj = 512; jj >= 32; jj >>= 1) {
        sm.kbuf[cur][tid]      = e0;
        sm.kbuf[cur][tid + NT] = e1;
        __syncthreads();
        ull p0 = sm.kbuf[cur][tid ^ jj];
        ull p1 = sm.kbuf[cur][(tid + NT) ^ jj];
        bool tm = (tid & jj) == 0;          // same bit for both slots (jj < 1024)
        e0 = tm ? (e0 > p0 ? e0 : p0) : (e0 < p0 ? e0 : p0);
        e1 = tm ? (e1 > p1 ? e1 : p1) : (e1 < p1 ? e1 : p1);
        cur ^= 1;
    }
    #pragma unroll
    for (int jj = 16; jj >= 1; jj >>= 1) {
        ull p0 = __shfl_xor_sync(FULL, e0, jj);
        ull p1 = __shfl_xor_sync(FULL, e1, jj);
        bool tm = (lane & jj) == 0;
        e0 = tm ? (e0 > p0 ? e0 : p0) : (e0 < p0 ? e0 : p0);
        e1 = tm ? (e1 > p1 ? e1 : p1) : (e1 < p1 ? e1 : p1);
    }
    sm.kbuf[cur][tid]      = e0;
    sm.kbuf[cur][tid + NT] = e1;
    __syncthreads();
    const ull* kk = sm.kbuf[cur];
    const float4* boxes = g_box + (size_t)b * NP;

    // ---- single-warp windowed greedy NMS (validated R6 logic) ----
    if (tid < 32) {
        int cnt = 0;
        for (int p = 0; p < NP && cnt < DETK; p += 32) {
            ull key = kk[p + lane];
            unsigned k32 = (unsigned)(key >> 32);
            bool valid = k32 >= 0x80000000u;
            if (__ballot_sync(FULL, valid) == 0) break;   // sorted: rest invalid

            int orig = NP - 1 - (int)(unsigned)key;
            float4 bx = boxes[orig];
            float  ar = (bx.z - bx.x) * (bx.w - bx.y);
            float  ap = ar + 1e-9f;

            // vs previously kept boxes
            bool sup = false;
            #pragma unroll 4
            for (int t = 0; t < cnt; ++t) {
                float4 kb = sm.kbox[t];
                float  ka = sm.karea[t];
                float iw = fmaxf(fminf(kb.z, bx.z) - fmaxf(kb.x, bx.x), 0.0f);
                float ih = fmaxf(fminf(kb.w, bx.w) - fmaxf(kb.y, bx.y), 0.0f);
                sup = sup || (3.5f * (iw * ih) > ka + ap);   // iou > 0.4
            }

            // intra-window suppression mask (bits i < lane only)
            sm.swbox[lane]  = bx;
            sm.swarea[lane] = ar;
            __syncwarp();
            unsigned supmask = 0u;
            #pragma unroll 8
            for (int i = 0; i < 32; ++i) {
                float4 b2 = sm.swbox[i];
                float  a2 = sm.swarea[i];
                float iw = fmaxf(fminf(b2.z, bx.z) - fmaxf(b2.x, bx.x), 0.0f);
                float ih = fmaxf(fminf(b2.w, bx.w) - fmaxf(b2.y, bx.y), 0.0f);
                bool s = (3.5f * (iw * ih) > a2 + ap) && (i < lane);
                supmask |= s ? (1u << i) : 0u;
            }

            // greedy resolve via ballots
            unsigned alive = __ballot_sync(FULL, valid && !sup);
            while (alive && cnt < DETK) {
                int i = __ffs(alive) - 1;
                if (lane == i) {
                    sm.kbox[cnt]    = bx;
                    sm.karea[cnt]   = ar;
                    sm.keepkey[cnt] = k32;
                }
                unsigned dead = __ballot_sync(FULL, (supmask >> i) & 1u);
                alive &= ~dead & ~(1u << i);
                cnt++;
            }
            __syncwarp();
        }
        if (lane == 0) sm.cnt = cnt;
    }
    __syncthreads();

    // ---- outputs [boxes 3200 | scores 800 | classes 800 | valid 800] ----
    if (tid < DETK) {
        int k = tid;
        float4 ob = make_float4(0.f, 0.f, 0.f, 0.f);
        float os = 0.f, oc = 0.f, ov = 0.f;
        if (k < sm.cnt) {
            ob = sm.kbox[k];
            os = s2f(sm.keepkey[k]);
            oc = 1.0f;
            ov = 1.0f;
        }
        float* obp = out + ((size_t)b * DETK + k) * 4;
        obp[0] = ob.x; obp[1] = ob.y; obp[2] = ob.z; obp[3] = ob.w;
        const int SB = BN * DETK * 4;   // 3200
        const int SC = BN * DETK;       // 800
        out[SB +          b * DETK + k] = os;
        out[SB + SC +     b * DETK + k] = oc;
        out[SB + 2 * SC + b * DETK + k] = ov;
    }
}

extern "C" void kernel_launch(void* const* d_in, const int* in_sizes, int n_in,
                              void* d_out, int out_size) {
    const float* clss  = (const float*)d_in[0];
    const float* regs  = (const float*)d_in[1];
    const float* qlts  = (const float*)d_in[2];
    const float* props = (const float*)d_in[3];
    float* out = (float*)d_out;

    k1_decode_sort<<<BN * 2, NT>>>(clss, regs, qlts, props);
    k2_merge_nms<<<BN, NT>>>(out);
}

// round 10
// speedup vs baseline: 1.2761x; 1.0084x over previous
#include <cuda_runtime.h>

#define BN   8
#define NP   2048
#define DETK 100
#define NT   1024
#define WIN  128
#define FULL 0xffffffffu

typedef unsigned long long ull;

// Inter-kernel scratch (allocation-free: __device__ globals)
__device__ ull    g_keys[BN * NP];
__device__ float4 g_box [BN * NP];

static __device__ __forceinline__ float stable_sigmoid(float d) {
    return (d >= 0.0f) ? (1.0f / (1.0f + expf(-d)))
                       : (expf(d) / (1.0f + expf(d)));
}
static __device__ __forceinline__ unsigned f2s(float f) {
    unsigned u = __float_as_uint(f);
    return (u & 0x80000000u) ? ~u : (u | 0x80000000u);
}
static __device__ __forceinline__ float s2f(unsigned u) {
    u = (u & 0x80000000u) ? (u & 0x7FFFFFFFu) : ~u;
    return __uint_as_float(u);
}

// ---------------- Kernel 1: decode half-image + sort its 1024 keys (unchanged R9) ----------------
__global__ __launch_bounds__(NT, 1)
void k1_decode_sort(const float* __restrict__ clss,
                    const float* __restrict__ regs,
                    const float* __restrict__ qlts,
                    const float* __restrict__ props)
{
    __shared__ ull kb[2][NT];

    const int b    = blockIdx.x >> 1;
    const int h    = blockIdx.x & 1;
    const int tid  = threadIdx.x;
    const int lane = tid & 31;
    const int g    = (h << 10) | tid;

    const float W_IMG = 1344.0f, H_IMG = 800.0f;
    const float CLIPV = 4.135166556742356f;   // log(1000/16)

    const float2* cls = (const float2*)(clss  + (size_t)b * NP * 2);
    const float4* reg = (const float4*)(regs  + (size_t)b * NP * 4);
    const float*  qlt =                 qlts  + (size_t)b * NP;
    const float4* prp = (const float4*)(props + (size_t)b * NP * 4);

    float4 p = prp[g];
    float bw = p.z - p.x, bh = p.w - p.y;
    float cx = p.x + 0.5f * bw, cy = p.y + 0.5f * bh;

    float4 r = reg[g];
    float dx = r.x * 0.1f;
    float dy = r.y * 0.1f;
    float dw = fminf(r.z * 0.2f, CLIPV);
    float dh = fminf(r.w * 0.2f, CLIPV);

    float pcx = dx * bw + cx;
    float pcy = dy * bh + cy;
    float pw  = expf(dw) * bw;
    float ph  = expf(dh) * bh;

    float x1 = fminf(fmaxf(pcx - 0.5f * pw, 0.0f), W_IMG);
    float y1 = fminf(fmaxf(pcy - 0.5f * ph, 0.0f), H_IMG);
    float x2 = fminf(fmaxf(pcx + 0.5f * pw, 0.0f), W_IMG);
    float y2 = fminf(fmaxf(pcy + 0.5f * ph, 0.0f), H_IMG);

    bool small_keep = ((x2 - x1) >= 0.01f) && ((y2 - y1) >= 0.01f);

    float2 c = cls[g];
    float raw = stable_sigmoid(c.y - c.x);
    bool  score_keep = raw > 0.5f;
    float score = stable_sigmoid(qlt[g]) * raw;

    bool valid = small_keep && score_keep;
    unsigned k32 = valid ? f2s(score) : 0u;   // valid <=> k32 >= 0x80000000

    g_box[b * NP + g] = make_float4(x1, y1, x2, y2);
    ull key = ((ull)k32 << 32) | (unsigned)(NP - 1 - g);

    // half-sort: direction from GLOBAL index g (half0 desc, half1 asc)
    int cur = 0;
    #pragma unroll
    for (int k = 2; k <= 1024; k <<= 1) {
        #pragma unroll
        for (int jj = k >> 1; jj > 0; jj >>= 1) {
            if (jj >= 32) {
                kb[cur][tid] = key;
                __syncthreads();
                ull pk = kb[cur][tid ^ jj];
                bool tm = ((g & k) == 0) != ((tid & jj) != 0);
                key = tm ? (key > pk ? key : pk) : (key < pk ? key : pk);
                cur ^= 1;
            } else {
                ull pk = __shfl_xor_sync(FULL, key, jj);
                bool tm = ((g & k) == 0) != ((lane & jj) != 0);
                key = tm ? (key > pk ? key : pk) : (key < pk ? key : pk);
            }
        }
    }
    g_keys[b * NP + g] = key;
}

// ---------------- Kernel 2: merge phase + mask-matrix NMS + output ----------------
struct Smem2 {
    ull      kbuf[2][NP];       // merge exchange buffers (32 KB)
    float4   wbox[WIN];         // window boxes (2 KB)
    float    warea[WIN];
    unsigned wkey[WIN];
    unsigned mask[WIN][4];      // kill masks: mask[j][wd] bit i2 -> j kills cand wd*32+i2 (2 KB)
    unsigned alive[4];          // valid && !suppressed-by-keeps, balloted
    float4   kbox[DETK];
    float    karea[DETK];
    unsigned keepkey[DETK];
    int      cnt;
    int      stop;
};

__global__ __launch_bounds__(NT, 1)
void k2_merge_nms(float* __restrict__ out)
{
    __shared__ Smem2 sm;

    const int b    = blockIdx.x;
    const int tid  = threadIdx.x;
    const int lane = tid & 31;

    ull e0 = g_keys[b * NP + tid];
    ull e1 = g_keys[b * NP + NT + tid];
    if (tid == 0) { sm.cnt = 0; sm.stop = 0; }

    // ---- final bitonic merge phase k=2048 (unchanged R9) ----
    {
        ull mx = e0 > e1 ? e0 : e1;
        ull mn = e0 > e1 ? e1 : e0;
        e0 = mx; e1 = mn;
    }
    int cur = 0;
    #pragma unroll
    for (int jj = 512; jj >= 32; jj >>= 1) {
        sm.kbuf[cur][tid]      = e0;
        sm.kbuf[cur][tid + NT] = e1;
        __syncthreads();
        ull p0 = sm.kbuf[cur][tid ^ jj];
        ull p1 = sm.kbuf[cur][(tid + NT) ^ jj];
        bool tm = (tid & jj) == 0;
        e0 = tm ? (e0 > p0 ? e0 : p0) : (e0 < p0 ? e0 : p0);
        e1 = tm ? (e1 > p1 ? e1 : p1) : (e1 < p1 ? e1 : p1);
        cur ^= 1;
    }
    #pragma unroll
    for (int jj = 16; jj >= 1; jj >>= 1) {
        ull p0 = __shfl_xor_sync(FULL, e0, jj);
        ull p1 = __shfl_xor_sync(FULL, e1, jj);
        bool tm = (lane & jj) == 0;
        e0 = tm ? (e0 > p0 ? e0 : p0) : (e0 < p0 ? e0 : p0);
        e1 = tm ? (e1 > p1 ? e1 : p1) : (e1 < p1 ? e1 : p1);
    }
    sm.kbuf[cur][tid]      = e0;
    sm.kbuf[cur][tid + NT] = e1;
    __syncthreads();
    const ull* kk = sm.kbuf[cur];
    const float4* boxes = g_box + (size_t)b * NP;

    // ---- mask-matrix windowed greedy NMS (128 candidates / round) ----
    int cnt = 0;
    for (int p = 0; p < NP; p += WIN) {
        // A: load window candidates
        if (tid < WIN) {
            ull key = kk[p + tid];
            unsigned k32 = (unsigned)(key >> 32);
            int orig = NP - 1 - (int)(unsigned)key;
            float4 bx = boxes[orig];
            sm.wkey[tid]  = k32;
            sm.wbox[tid]  = bx;
            sm.warea[tid] = (bx.z - bx.x) * (bx.w - bx.y);
        }
        __syncthreads();

        // B1: kill-mask build (threads 0..511): j = tid&127, wd = tid>>7
        if (tid < 512) {
            int j  = tid & 127;
            int wd = tid >> 7;
            float4 bj = sm.wbox[j];
            float  aj = sm.warea[j];
            unsigned m = 0u;
            #pragma unroll 8
            for (int i2 = 0; i2 < 32; ++i2) {
                int i = (wd << 5) | i2;
                float4 bi  = sm.wbox[i];
                float  api = sm.warea[i] + 1e-9f;
                float iw = fmaxf(fminf(bj.z, bi.z) - fmaxf(bj.x, bi.x), 0.0f);
                float ih = fmaxf(fminf(bj.w, bi.w) - fmaxf(bj.y, bi.y), 0.0f);
                bool kill = (3.5f * (iw * ih) > aj + api) && (i > j);   // iou > 0.4
                m |= kill ? (1u << i2) : 0u;
            }
            sm.mask[j][wd] = m;
        }
        // B2: vs-previous-keeps + validity -> alive words (warps 16..19)
        else if (tid < 640) {
            int i = tid - 512;            // candidate 0..127; warp 16+wd handles word wd
            float4 bi  = sm.wbox[i];
            float  api = sm.warea[i] + 1e-9f;
            bool sup = false;
            #pragma unroll 4
            for (int t = 0; t < cnt; ++t) {
                float4 kb = sm.kbox[t];
                float  ka = sm.karea[t];
                float iw = fmaxf(fminf(kb.z, bi.z) - fmaxf(kb.x, bi.x), 0.0f);
                float ih = fmaxf(fminf(kb.w, bi.w) - fmaxf(kb.y, bi.y), 0.0f);
                sup = sup || (3.5f * (iw * ih) > ka + api);
            }
            bool ok = (sm.wkey[i] >= 0x80000000u) && !sup;
            unsigned aw = __ballot_sync(FULL, ok);
            if (lane == 0) sm.alive[i >> 5] = aw;
        }
        __syncthreads();

        // C: serial greedy resolve (thread 0) — exact sequential semantics
        if (tid == 0) {
            unsigned a0 = sm.alive[0], a1 = sm.alive[1], a2 = sm.alive[2], a3 = sm.alive[3];
            int c = cnt;
            while (a0 && c < DETK) {
                int i = __ffs(a0) - 1;
                a0 &= a0 - 1;
                sm.kbox[c] = sm.wbox[i]; sm.karea[c] = sm.warea[i]; sm.keepkey[c] = sm.wkey[i];
                c++;
                a0 &= ~sm.mask[i][0]; a1 &= ~sm.mask[i][1];
                a2 &= ~sm.mask[i][2]; a3 &= ~sm.mask[i][3];
            }
            while (a1 && c < DETK) {
                int i2 = __ffs(a1) - 1; int i = 32 + i2;
                a1 &= a1 - 1;
                sm.kbox[c] = sm.wbox[i]; sm.karea[c] = sm.warea[i]; sm.keepkey[c] = sm.wkey[i];
                c++;
                a1 &= ~sm.mask[i][1]; a2 &= ~sm.mask[i][2]; a3 &= ~sm.mask[i][3];
            }
            while (a2 && c < DETK) {
                int i2 = __ffs(a2) - 1; int i = 64 + i2;
                a2 &= a2 - 1;
                sm.kbox[c] = sm.wbox[i]; sm.karea[c] = sm.warea[i]; sm.keepkey[c] = sm.wkey[i];
                c++;
                a2 &= ~sm.mask[i][2]; a3 &= ~sm.mask[i][3];
            }
            while (a3 && c < DETK) {
                int i2 = __ffs(a3) - 1; int i = 96 + i2;
                a3 &= a3 - 1;
                sm.kbox[c] = sm.wbox[i]; sm.karea[c] = sm.warea[i]; sm.keepkey[c] = sm.wkey[i];
                c++;
                a3 &= ~sm.mask[i][3];
            }
            sm.cnt  = c;
            sm.stop = (c >= DETK || sm.wkey[WIN - 1] < 0x80000000u) ? 1 : 0;
        }
        __syncthreads();
        cnt = sm.cnt;
        if (sm.stop) break;
    }

    // ---- outputs [boxes 3200 | scores 800 | classes 800 | valid 800] ----
    if (tid < DETK) {
        int k = tid;
        float4 ob = make_float4(0.f, 0.f, 0.f, 0.f);
        float os = 0.f, oc = 0.f, ov = 0.f;
        if (k < cnt) {
            ob = sm.kbox[k];
            os = s2f(sm.keepkey[k]);
            oc = 1.0f;
            ov = 1.0f;
        }
        float* obp = out + ((size_t)b * DETK + k) * 4;
        obp[0] = ob.x; obp[1] = ob.y; obp[2] = ob.z; obp[3] = ob.w;
        const int SB = BN * DETK * 4;   // 3200
        const int SC = BN * DETK;       // 800
        out[SB +          b * DETK + k] = os;
        out[SB + SC +     b * DETK + k] = oc;
        out[SB + 2 * SC + b * DETK + k] = ov;
    }
}

extern "C" void kernel_launch(void* const* d_in, const int* in_sizes, int n_in,
                              void* d_out, int out_size) {
    const float* clss  = (const float*)d_in[0];
    const float* regs  = (const float*)d_in[1];
    const float* qlts  = (const float*)d_in[2];
    const float* props = (const float*)d_in[3];
    float* out = (float*)d_out;

    k1_decode_sort<<<BN * 2, NT>>>(clss, regs, qlts, props);
    k2_merge_nms<<<BN, NT>>>(out);
}

// round 11
// speedup vs baseline: 1.5772x; 1.2359x over previous
#include <cuda_runtime.h>

#define BN   8
#define NP   2048
#define DETK 100
#define NT   1024
#define WIN  128
#define FULL 0xffffffffu

typedef unsigned long long ull;

// Inter-kernel scratch (allocation-free: __device__ globals)
__device__ ull    g_keys[BN * NP];
__device__ float4 g_box [BN * NP];

static __device__ __forceinline__ float stable_sigmoid(float d) {
    return (d >= 0.0f) ? (1.0f / (1.0f + expf(-d)))
                       : (expf(d) / (1.0f + expf(d)));
}
static __device__ __forceinline__ unsigned f2s(float f) {
    unsigned u = __float_as_uint(f);
    return (u & 0x80000000u) ? ~u : (u | 0x80000000u);
}
static __device__ __forceinline__ float s2f(unsigned u) {
    u = (u & 0x80000000u) ? (u & 0x7FFFFFFFu) : ~u;
    return __uint_as_float(u);
}

// ---------------- Kernel 1: decode half-image + sort its 1024 keys (unchanged) ----------------
__global__ __launch_bounds__(NT, 1)
void k1_decode_sort(const float* __restrict__ clss,
                    const float* __restrict__ regs,
                    const float* __restrict__ qlts,
                    const float* __restrict__ props)
{
    __shared__ ull kb[2][NT];

    const int b    = blockIdx.x >> 1;
    const int h    = blockIdx.x & 1;
    const int tid  = threadIdx.x;
    const int lane = tid & 31;
    const int g    = (h << 10) | tid;

    const float W_IMG = 1344.0f, H_IMG = 800.0f;
    const float CLIPV = 4.135166556742356f;   // log(1000/16)

    const float2* cls = (const float2*)(clss  + (size_t)b * NP * 2);
    const float4* reg = (const float4*)(regs  + (size_t)b * NP * 4);
    const float*  qlt =                 qlts  + (size_t)b * NP;
    const float4* prp = (const float4*)(props + (size_t)b * NP * 4);

    float4 p = prp[g];
    float bw = p.z - p.x, bh = p.w - p.y;
    float cx = p.x + 0.5f * bw, cy = p.y + 0.5f * bh;

    float4 r = reg[g];
    float dx = r.x * 0.1f;
    float dy = r.y * 0.1f;
    float dw = fminf(r.z * 0.2f, CLIPV);
    float dh = fminf(r.w * 0.2f, CLIPV);

    float pcx = dx * bw + cx;
    float pcy = dy * bh + cy;
    float pw  = expf(dw) * bw;
    float ph  = expf(dh) * bh;

    float x1 = fminf(fmaxf(pcx - 0.5f * pw, 0.0f), W_IMG);
    float y1 = fminf(fmaxf(pcy - 0.5f * ph, 0.0f), H_IMG);
    float x2 = fminf(fmaxf(pcx + 0.5f * pw, 0.0f), W_IMG);
    float y2 = fminf(fmaxf(pcy + 0.5f * ph, 0.0f), H_IMG);

    bool small_keep = ((x2 - x1) >= 0.01f) && ((y2 - y1) >= 0.01f);

    float2 c = cls[g];
    float raw = stable_sigmoid(c.y - c.x);
    bool  score_keep = raw > 0.5f;
    float score = stable_sigmoid(qlt[g]) * raw;

    bool valid = small_keep && score_keep;
    unsigned k32 = valid ? f2s(score) : 0u;   // valid <=> k32 >= 0x80000000

    g_box[b * NP + g] = make_float4(x1, y1, x2, y2);
    ull key = ((ull)k32 << 32) | (unsigned)(NP - 1 - g);

    // half-sort: direction from GLOBAL index g (half0 desc, half1 asc)
    int cur = 0;
    #pragma unroll
    for (int k = 2; k <= 1024; k <<= 1) {
        #pragma unroll
        for (int jj = k >> 1; jj > 0; jj >>= 1) {
            if (jj >= 32) {
                kb[cur][tid] = key;
                __syncthreads();
                ull pk = kb[cur][tid ^ jj];
                bool tm = ((g & k) == 0) != ((tid & jj) != 0);
                key = tm ? (key > pk ? key : pk) : (key < pk ? key : pk);
                cur ^= 1;
            } else {
                ull pk = __shfl_xor_sync(FULL, key, jj);
                bool tm = ((g & k) == 0) != ((lane & jj) != 0);
                key = tm ? (key > pk ? key : pk) : (key < pk ? key : pk);
            }
        }
    }
    g_keys[b * NP + g] = key;
}

// ---------------- Kernel 2: merge + alive-predicated mask NMS + output ----------------
struct Smem2 {
    ull      kbuf[2][NP];            // merge exchange buffers (32 KB)
    float4   wbox[WIN];
    float    warea[WIN];
    unsigned wkey[WIN];
    alignas(16) unsigned mask[WIN][4];  // kill masks (rows 16B-aligned for LDS.128)
    unsigned alive[4];
    float4   kbox[DETK];
    float    karea[DETK];
    unsigned keepkey[DETK];
    int      keepwin[DETK];          // window-local index of each keep this window
    int      cnt;
    int      stop;
};

__global__ __launch_bounds__(NT, 1)
void k2_merge_nms(float* __restrict__ out)
{
    __shared__ Smem2 sm;

    const int b    = blockIdx.x;
    const int tid  = threadIdx.x;
    const int lane = tid & 31;

    ull e0 = g_keys[b * NP + tid];
    ull e1 = g_keys[b * NP + NT + tid];

    // ---- final bitonic merge phase k=2048 ----
    {
        ull mx = e0 > e1 ? e0 : e1;
        ull mn = e0 > e1 ? e1 : e0;
        e0 = mx; e1 = mn;
    }
    int cur = 0;
    #pragma unroll
    for (int jj = 512; jj >= 32; jj >>= 1) {
        sm.kbuf[cur][tid]      = e0;
        sm.kbuf[cur][tid + NT] = e1;
        __syncthreads();
        ull p0 = sm.kbuf[cur][tid ^ jj];
        ull p1 = sm.kbuf[cur][(tid + NT) ^ jj];
        bool tm = (tid & jj) == 0;
        e0 = tm ? (e0 > p0 ? e0 : p0) : (e0 < p0 ? e0 : p0);
        e1 = tm ? (e1 > p1 ? e1 : p1) : (e1 < p1 ? e1 : p1);
        cur ^= 1;
    }
    #pragma unroll
    for (int jj = 16; jj >= 1; jj >>= 1) {
        ull p0 = __shfl_xor_sync(FULL, e0, jj);
        ull p1 = __shfl_xor_sync(FULL, e1, jj);
        bool tm = (lane & jj) == 0;
        e0 = tm ? (e0 > p0 ? e0 : p0) : (e0 < p0 ? e0 : p0);
        e1 = tm ? (e1 > p1 ? e1 : p1) : (e1 < p1 ? e1 : p1);
    }
    sm.kbuf[cur][tid]      = e0;
    sm.kbuf[cur][tid + NT] = e1;
    __syncthreads();
    const ull* kk = sm.kbuf[cur];
    const float4* boxes = g_box + (size_t)b * NP;

    // ---- windowed greedy NMS: B2(alive) -> B1(masks, predicated) -> resolve -> copy ----
    int cnt = 0;
    for (int p = 0; p < NP; p += WIN) {
        // A: load window (threads 0..127)
        if (tid < WIN) {
            ull key = kk[p + tid];
            unsigned k32 = (unsigned)(key >> 32);
            int orig = NP - 1 - (int)(unsigned)key;
            float4 bx = boxes[orig];
            sm.wkey[tid]  = k32;
            sm.wbox[tid]  = bx;
            sm.warea[tid] = (bx.z - bx.x) * (bx.w - bx.y);
        }
        // B2: vs-previous-keeps survival (threads 512..639, own loads, early break)
        else if (tid >= 512 && tid < 640) {
            int i = tid - 512;
            ull key = kk[p + i];
            unsigned k32 = (unsigned)(key >> 32);
            bool ok = k32 >= 0x80000000u;
            if (ok) {
                int orig = NP - 1 - (int)(unsigned)key;
                float4 bi = boxes[orig];
                float api = (bi.z - bi.x) * (bi.w - bi.y) + 1e-9f;
                for (int t = 0; t < cnt; ++t) {
                    float4 kb = sm.kbox[t];
                    float  ka = sm.karea[t];
                    float iw = fmaxf(fminf(kb.z, bi.z) - fmaxf(kb.x, bi.x), 0.0f);
                    float ih = fmaxf(fminf(kb.w, bi.w) - fmaxf(kb.y, bi.y), 0.0f);
                    if (3.5f * (iw * ih) > ka + api) { ok = false; break; }   // iou > 0.4
                }
            }
            unsigned aw = __ballot_sync(FULL, ok);
            if (lane == 0) sm.alive[i >> 5] = aw;
        }
        __syncthreads();

        // B1: kill masks, only for alive j; triangular words are zero
        if (tid < 512) {
            int j  = tid & 127;
            int wd = tid >> 7;
            bool jal = (sm.alive[j >> 5] >> (j & 31)) & 1u;
            if (jal) {
                if (((wd << 5) | 31) <= j) {
                    sm.mask[j][wd] = 0u;          // all i in word <= j
                } else {
                    float4 bj = sm.wbox[j];
                    float  aj = sm.warea[j];
                    unsigned m = 0u;
                    #pragma unroll 8
                    for (int i2 = 0; i2 < 32; ++i2) {
                        int i = (wd << 5) | i2;
                        float4 bi  = sm.wbox[i];
                        float  api = sm.warea[i] + 1e-9f;
                        float iw = fmaxf(fminf(bj.z, bi.z) - fmaxf(bj.x, bi.x), 0.0f);
                        float ih = fmaxf(fminf(bj.w, bi.w) - fmaxf(bj.y, bi.y), 0.0f);
                        bool kill = (3.5f * (iw * ih) > aj + api) && (i > j);
                        m |= kill ? (1u << i2) : 0u;
                    }
                    sm.mask[j][wd] = m;
                }
            }
        }
        __syncthreads();

        // C: serial greedy resolve (thread 0) — append indices only
        if (tid == 0) {
            unsigned a0 = sm.alive[0], a1 = sm.alive[1], a2 = sm.alive[2], a3 = sm.alive[3];
            int c = cnt;
            while (a0 && c < DETK) {
                int i = __ffs(a0) - 1;
                a0 &= a0 - 1;
                uint4 m = *reinterpret_cast<const uint4*>(sm.mask[i]);
                a0 &= ~m.x; a1 &= ~m.y; a2 &= ~m.z; a3 &= ~m.w;
                sm.keepwin[c++] = i;
            }
            while (a1 && c < DETK) {
                int i = 32 + (__ffs(a1) - 1);
                a1 &= a1 - 1;
                uint4 m = *reinterpret_cast<const uint4*>(sm.mask[i]);
                a1 &= ~m.y; a2 &= ~m.z; a3 &= ~m.w;
                sm.keepwin[c++] = i;
            }
            while (a2 && c < DETK) {
                int i = 64 + (__ffs(a2) - 1);
                a2 &= a2 - 1;
                uint4 m = *reinterpret_cast<const uint4*>(sm.mask[i]);
                a2 &= ~m.z; a3 &= ~m.w;
                sm.keepwin[c++] = i;
            }
            while (a3 && c < DETK) {
                int i = 96 + (__ffs(a3) - 1);
                a3 &= a3 - 1;
                uint4 m = *reinterpret_cast<const uint4*>(sm.mask[i]);
                a3 &= ~m.w;
                sm.keepwin[c++] = i;
            }
            sm.cnt  = c;
            sm.stop = (c >= DETK || sm.wkey[WIN - 1] < 0x80000000u) ? 1 : 0;
        }
        __syncthreads();

        // D: parallel copy of new keeps into the keep list
        int newcnt = sm.cnt;
        int stop   = sm.stop;
        if (tid >= cnt && tid < newcnt) {
            int i = sm.keepwin[tid];
            sm.kbox[tid]    = sm.wbox[i];
            sm.karea[tid]   = sm.warea[i];
            sm.keepkey[tid] = sm.wkey[i];
        }
        __syncthreads();    // kbox visible for next B2; wbox free for next A
        cnt = newcnt;
        if (stop) break;
    }

    // ---- outputs [boxes 3200 | scores 800 | classes 800 | valid 800] ----
    if (tid < DETK) {
        int k = tid;
        float4 ob = make_float4(0.f, 0.f, 0.f, 0.f);
        float os = 0.f, oc = 0.f, ov = 0.f;
        if (k < cnt) {
            ob = sm.kbox[k];
            os = s2f(sm.keepkey[k]);
            oc = 1.0f;
            ov = 1.0f;
        }
        float* obp = out + ((size_t)b * DETK + k) * 4;
        obp[0] = ob.x; obp[1] = ob.y; obp[2] = ob.z; obp[3] = ob.w;
        const int SB = BN * DETK * 4;   // 3200
        const int SC = BN * DETK;       // 800
        out[SB +          b * DETK + k] = os;
        out[SB + SC +     b * DETK + k] = oc;
        out[SB + 2 * SC + b * DETK + k] = ov;
    }
}

extern "C" void kernel_launch(void* const* d_in, const int* in_sizes, int n_in,
                              void* d_out, int out_size) {
    const float* clss  = (const float*)d_in[0];
    const float* regs  = (const float*)d_in[1];
    const float* qlts  = (const float*)d_in[2];
    const float* props = (const float*)d_in[3];
    float* out = (float*)d_out;

    k1_decode_sort<<<BN * 2, NT>>>(clss, regs, qlts, props);
    k2_merge_nms<<<BN, NT>>>(out);
}